// round 13
// baseline (speedup 1.0000x reference)
#include <cuda_runtime.h>
#include <cstdint>

#define BINS        10
#define THREADS     384
#define NWARPS      (THREADS / 32)        // 12
#define CTAS_PER_SM 2
#define GRID        (148 * CTAS_PER_SM)   // 296
#define STAGES      4

#define TILE_ELEMS  1536                  // one float4 per thread per stream
#define TILE_BYTES  (TILE_ELEMS * 4)      // 6144 B per stream
#define STAGE_BYTES (2 * TILE_BYTES)      // 12288 B (inp + tgt)

// Dynamic smem layout
#define OFF_FULL    0
#define OFF_EMPTY   (STAGES * 8)
#define OFF_TILES   128
#define OFF_HIST    (OFF_TILES + STAGES * STAGE_BYTES)          // 49280
#define SMEM_TOTAL  (OFF_HIST + BINS * THREADS * 8)             // 80000 B

// Global scratch (allocation-free). Zero at every kernel entry: zero-init at
// load, last CTA resets after writing out (graph-replay safe).
__device__ float        g_binS[BINS];
__device__ float        g_binC[BINS];
__device__ unsigned int g_ticket;

// ---------------- PTX helpers ----------------
__device__ __forceinline__ uint32_t smem_u32(const void* p) {
    uint32_t a;
    asm("{ .reg .u64 t; cvta.to.shared.u64 t, %1; cvt.u32.u64 %0, t; }"
        : "=r"(a) : "l"(p));
    return a;
}
#define MBAR_INIT(addr, cnt) \
    asm volatile("mbarrier.init.shared.b64 [%0], %1;" :: "r"(addr), "r"(cnt) : "memory")
#define MBAR_EXPECT_TX(addr, bytes) \
    asm volatile("mbarrier.arrive.expect_tx.shared.b64 _, [%0], %1;" :: "r"(addr), "r"(bytes) : "memory")
#define MBAR_ARRIVE(addr) \
    asm volatile("mbarrier.arrive.shared.b64 _, [%0];" :: "r"(addr) : "memory")
#define MBAR_WAIT(addr, par) do {                                              \
    asm volatile("{\n\t.reg .pred P;\n\t"                                      \
        "W%=:\n\t"                                                             \
        "mbarrier.try_wait.parity.acquire.cta.shared::cta.b64 P, [%0], %1, 0x989680;\n\t" \
        "@P bra.uni D%=;\n\t"                                                  \
        "bra.uni W%=;\n\t"                                                     \
        "D%=:\n\t}" :: "r"(addr), "r"(par) : "memory");                        \
} while (0)
#define MBAR_WAIT_RELAXED(addr, par) do {                                      \
    asm volatile("{\n\t.reg .pred P;\n\t"                                      \
        "W%=:\n\t"                                                             \
        "mbarrier.try_wait.parity.relaxed.cta.shared::cta.b64 P, [%0], %1, 0x989680;\n\t" \
        "@P bra.uni D%=;\n\t"                                                  \
        "bra.uni W%=;\n\t"                                                     \
        "D%=:\n\t}" :: "r"(addr), "r"(par) : "memory");                        \
} while (0)
__device__ __forceinline__ void bulk_g2s(uint32_t dst, const void* src,
                                         uint32_t bytes, uint32_t mbar) {
    asm volatile(
        "cp.async.bulk.shared::cta.global.mbarrier::complete_tx::bytes [%0], [%1], %2, [%3];"
        :: "r"(dst), "l"(src), "r"(bytes), "r"(mbar) : "memory");
}

// Bin index matches reference bit-for-bit: g = |p-t| fp32, idx = trunc(g*10)
// clipped to 9. bce = -log(t ? p : 1-p) = -log(1-g) for t in {0,1}.
// Slot hist[idx*THREADS + tid]: 32 lanes -> consecutive 8B slots, conflict-
// free; single writer per slot -> deterministic.
__device__ __forceinline__ void ghm_accum(float p, float t, float2* hist_tid) {
    float g   = fabsf(p - t);
    int   idx = min((int)(g * 10.0f), BINS - 1);
    float bce = -__logf(1.0f - g);
    float2* slot = hist_tid + idx * THREADS;
    float2  a = *slot;
    a.x += bce;
    a.y += 1.0f;
    *slot = a;
}

__global__ void __launch_bounds__(THREADS)
ghm_tma_kernel(const float* __restrict__ inp,
               const float* __restrict__ tgt,
               int ntiles, int n,
               float* __restrict__ out) {
    extern __shared__ char smem[];
    __shared__ float2 scratch[BINS][NWARPS];
    __shared__ bool   s_is_last;

    const uint32_t sb   = smem_u32(smem);
    const int      tid  = threadIdx.x;
    const int      lane = tid & 31;
    const int      wid  = tid >> 5;
    const int      bid  = blockIdx.x;
    float2* hist = (float2*)(smem + OFF_HIST);

    #pragma unroll
    for (int b = 0; b < BINS; b++)
        hist[b * THREADS + tid] = make_float2(0.0f, 0.0f);

    if (tid == 0) {
        #pragma unroll
        for (int s = 0; s < STAGES; s++) {
            MBAR_INIT(sb + OFF_FULL  + s * 8, 1);
            MBAR_INIT(sb + OFF_EMPTY + s * 8, NWARPS);
        }
    }
    __syncthreads();

    // Local tiles: global tile = bid + k*GRID.
    int nloc = (bid < ntiles) ? (ntiles - bid + GRID - 1) / GRID : 0;

    // ---- producer prologue (thread 0): fill all stages ----
    int issued = 0, pstage = 0, pphase = 1;   // parity 1: first waits pass
    if (tid == 0) {
        int pre = min(STAGES, nloc);
        for (; issued < pre; issued++) {
            long long gt = (long long)(bid + (long long)issued * GRID);
            uint32_t dst = sb + OFF_TILES + pstage * STAGE_BYTES;
            uint32_t fb  = sb + OFF_FULL + pstage * 8;
            MBAR_EXPECT_TX(fb, STAGE_BYTES);
            bulk_g2s(dst,              (const char*)inp + gt * TILE_BYTES, TILE_BYTES, fb);
            bulk_g2s(dst + TILE_BYTES, (const char*)tgt + gt * TILE_BYTES, TILE_BYTES, fb);
            if (++pstage == STAGES) { pstage = 0; pphase ^= 1; }
        }
    }

    // ---- main loop: consume one stage, refill it for STAGES ahead ----
    float2* hist_tid = &hist[tid];
    int cstage = 0, cphase = 0;
    for (int k = 0; k < nloc; k++) {
        MBAR_WAIT(sb + OFF_FULL + cstage * 8, cphase);
        const float4* P = (const float4*)(smem + OFF_TILES + cstage * STAGE_BYTES);
        const float4* T = (const float4*)((const char*)P + TILE_BYTES);
        float4 p = P[tid];
        float4 t = T[tid];
        ghm_accum(p.x, t.x, hist_tid);
        ghm_accum(p.y, t.y, hist_tid);
        ghm_accum(p.z, t.z, hist_tid);
        ghm_accum(p.w, t.w, hist_tid);
        if (lane == 0) MBAR_ARRIVE(sb + OFF_EMPTY + cstage * 8);
        if (++cstage == STAGES) { cstage = 0; cphase ^= 1; }

        if (tid == 0 && issued < nloc) {
            MBAR_WAIT_RELAXED(sb + OFF_EMPTY + pstage * 8, pphase);
            long long gt = (long long)(bid + (long long)issued * GRID);
            uint32_t dst = sb + OFF_TILES + pstage * STAGE_BYTES;
            uint32_t fb  = sb + OFF_FULL + pstage * 8;
            MBAR_EXPECT_TX(fb, STAGE_BYTES);
            bulk_g2s(dst,              (const char*)inp + gt * TILE_BYTES, TILE_BYTES, fb);
            bulk_g2s(dst + TILE_BYTES, (const char*)tgt + gt * TILE_BYTES, TILE_BYTES, fb);
            issued++;
            if (++pstage == STAGES) { pstage = 0; pphase ^= 1; }
        }
    }

    // Tail elements beyond whole tiles (LDG grid-stride).
    for (long long i = (long long)ntiles * TILE_ELEMS + (long long)bid * THREADS + tid;
         i < n; i += (long long)GRID * THREADS)
        ghm_accum(inp[i], tgt[i], hist_tid);

    __syncthreads();

    // Warp-shuffle reduction of the per-thread-private histograms.
    #pragma unroll
    for (int b = 0; b < BINS; b++) {
        float2 v = hist[b * THREADS + tid];
        #pragma unroll
        for (int off = 16; off > 0; off >>= 1) {
            v.x += __shfl_down_sync(0xFFFFFFFFu, v.x, off);
            v.y += __shfl_down_sync(0xFFFFFFFFu, v.y, off);
        }
        if (lane == 0) scratch[b][wid] = v;
    }
    __syncthreads();

    if (tid < BINS) {
        float2 s = scratch[tid][0];
        #pragma unroll
        for (int w = 1; w < NWARPS; w++) {
            s.x += scratch[tid][w].x;
            s.y += scratch[tid][w].y;
        }
        atomicAdd(&g_binS[tid], s.x);
        atomicAdd(&g_binC[tid], s.y);
    }
    __threadfence();
    __syncthreads();

    if (tid == 0)
        s_is_last = (atomicAdd(&g_ticket, 1u) == GRID - 1);
    __syncthreads();

    if (s_is_last && tid == 0) {
        __threadfence();
        float nb = 0.0f, accv = 0.0f;
        #pragma unroll
        for (int b = 0; b < BINS; b++) {
            float c = __ldcg(&g_binC[b]);
            float s = __ldcg(&g_binS[b]);
            if (c > 0.0f) { nb += 1.0f; accv += s / c; }
        }
        out[0] = accv / fmaxf(nb, 1.0f);
        #pragma unroll
        for (int b = 0; b < BINS; b++) { g_binS[b] = 0.0f; g_binC[b] = 0.0f; }
        g_ticket = 0u;
    }
}

extern "C" void kernel_launch(void* const* d_in, const int* in_sizes, int n_in,
                              void* d_out, int out_size) {
    const float* inp = (const float*)d_in[0];
    const float* tgt = (const float*)d_in[1];
    float* out = (float*)d_out;
    int n      = in_sizes[0];
    int ntiles = n / TILE_ELEMS;

    cudaFuncSetAttribute(ghm_tma_kernel,
                         cudaFuncAttributeMaxDynamicSharedMemorySize, SMEM_TOTAL);
    ghm_tma_kernel<<<GRID, THREADS, SMEM_TOTAL>>>(inp, tgt, ntiles, n, out);
}